// round 8
// baseline (speedup 1.0000x reference)
#include <cuda_runtime.h>
#include <math.h>

// Problem constants
#define BB 16
#define NPIX (288 * 800)        // 230400 pixels per batch per plane
#define NVEC (NPIX / 4)         // 57600 float4 groups per plane per batch
#define BPB 45                  // blocks per batch -> 720 total (<=740 resident @5/SM)
#define GB  (BPB * BB)          // 720
#define TPB 256
#define KIT 5                   // exactly 5 groups/thread: 45*256*5 = 57600
#define NL 4                    // tracked labels 1..4 (label 0 stats dead)
#define NP1 20                  // 16 sums + 4 counts
#define NP2 5                   // 4 hinge + wnll
#define DELTA_V 0.5f

// Scratch (device globals; allocation is forbidden)
__device__ float g_p1[BB][BPB][NP1];   // pass1 per-block partials
__device__ float g_p2[BB][BPB][NP2];   // pass2 per-block partials
__device__ float g_cnts[BB][NL];       // written by pass2 blk==0 of each batch
__device__ int   g_t2;                 // pass2 finalize ticket (reset each replay)

__device__ __forceinline__ float warp_sum(float v) {
    #pragma unroll
    for (int o = 16; o > 0; o >>= 1) v += __shfl_xor_sync(0xffffffffu, v, o);
    return v;
}

// L2 evict_last via cache-policy operand (legal at any load width, unlike the
// bare .L2::evict_last qualifier which sm_100 ptxas restricts to 256-bit).
__device__ __forceinline__ unsigned long long mk_evict_last_policy() {
    unsigned long long pol;
    asm("createpolicy.fractional.L2::evict_last.b64 %0, 1.0;" : "=l"(pol));
    return pol;
}
__device__ __forceinline__ float4 ldg_el_f4(const float4* p, unsigned long long pol) {
    float4 v;
    asm volatile("ld.global.nc.L2::cache_hint.v4.f32 {%0,%1,%2,%3}, [%4], %5;"
                 : "=f"(v.x), "=f"(v.y), "=f"(v.z), "=f"(v.w)
                 : "l"(p), "l"(pol));
    return v;
}
__device__ __forceinline__ int4 ldg_el_i4(const int4* p, unsigned long long pol) {
    int4 v;
    asm volatile("ld.global.nc.L2::cache_hint.v4.s32 {%0,%1,%2,%3}, [%4], %5;"
                 : "=r"(v.x), "=r"(v.y), "=r"(v.z), "=r"(v.w)
                 : "l"(p), "l"(pol));
    return v;
}

// ---------------------------------------------------------------------------
// Pass 1: per-(b,label) embedding sums + counts only.
// grid=(45,16), block=256, 5 blocks/SM.
__global__ void __launch_bounds__(TPB, 5)
pass1_kernel(const float* __restrict__ emb,
             const int*   __restrict__ lab) {
    const int b   = blockIdx.y;
    const int blk = blockIdx.x;
    const int tid = threadIdx.x;
    const float* e0 = emb + (size_t)b * 4 * NPIX;
    const int*   l0 = lab + (size_t)b * NPIX;
    const int base = blk * (TPB * KIT) + tid;
    const unsigned long long pol = mk_evict_last_policy();

    float acc[NL][4];
    float cnt[NL];
    #pragma unroll
    for (int l = 0; l < NL; l++) {
        cnt[l] = 0.f;
        #pragma unroll
        for (int d = 0; d < 4; d++) acc[l][d] = 0.f;
    }

    #pragma unroll
    for (int k = 0; k < KIT; k++) {
        const int i = base + k * TPB;
        float4 e0v = ldg_el_f4((const float4*)(e0)          + i, pol);
        float4 e1v = ldg_el_f4((const float4*)(e0 + NPIX)   + i, pol);
        float4 e2v = ldg_el_f4((const float4*)(e0 + 2*NPIX) + i, pol);
        float4 e3v = ldg_el_f4((const float4*)(e0 + 3*NPIX) + i, pol);
        int4   lv  = ldg_el_i4((const int4*)(l0) + i, pol);

        const float ed0[4] = {e0v.x, e0v.y, e0v.z, e0v.w};
        const float ed1[4] = {e1v.x, e1v.y, e1v.z, e1v.w};
        const float ed2[4] = {e2v.x, e2v.y, e2v.z, e2v.w};
        const float ed3[4] = {e3v.x, e3v.y, e3v.z, e3v.w};
        const int   lbs[4] = {lv.x, lv.y, lv.z, lv.w};

        #pragma unroll
        for (int p = 0; p < 4; p++) {
            const int L = lbs[p];
            #pragma unroll
            for (int l = 0; l < NL; l++) {
                if (L == l + 1) {
                    acc[l][0] += ed0[p];
                    acc[l][1] += ed1[p];
                    acc[l][2] += ed2[p];
                    acc[l][3] += ed3[p];
                    cnt[l]    += 1.f;
                }
            }
        }
    }

    // block reduce 20 values -> per-block partial
    __shared__ float sh[TPB / 32][NP1];
    const int wid = tid >> 5, lane = tid & 31;
    float vals[NP1];
    #pragma unroll
    for (int l = 0; l < NL; l++) {
        #pragma unroll
        for (int d = 0; d < 4; d++) vals[l * 4 + d] = acc[l][d];
        vals[16 + l] = cnt[l];
    }
    #pragma unroll
    for (int j = 0; j < NP1; j++) {
        float r = warp_sum(vals[j]);
        if (lane == 0) sh[wid][j] = r;
    }
    __syncthreads();
    if (tid < NP1) {
        float s = 0.f;
        #pragma unroll
        for (int w = 0; w < TPB / 32; w++) s += sh[w][tid];
        g_p1[b][blk][tid] = s;
    }
}

// ---------------------------------------------------------------------------
// Pass 2: each block (a) redundantly reduces its batch's pass1 partials to
// means (deterministic fixed order), (b) computes hinge + weighted CE over
// its slice, (c) last block finalizes the scalar loss.
__global__ void __launch_bounds__(TPB, 5)
pass2_kernel(const float* __restrict__ emb,
             const float* __restrict__ seg2,
             const int*   __restrict__ lab,
             float* __restrict__ out) {
    const int b   = blockIdx.y;
    const int blk = blockIdx.x;
    const int tid = threadIdx.x;
    const float* e0 = emb  + (size_t)b * 4 * NPIX;
    const float* s0 = seg2 + (size_t)b * 2 * NPIX;
    const int*   l0 = lab  + (size_t)b * NPIX;
    const int base = blk * (TPB * KIT) + tid;
    const unsigned long long pol = mk_evict_last_policy();

    // ---- means from pass1 partials (every block, deterministic) ----
    __shared__ float red[NP1][8];
    __shared__ float tot[NP1];
    __shared__ float sm[NL][4];
    if (tid < NP1 * 8) {
        const int col = tid >> 3, sub = tid & 7;
        float s = 0.f;
        for (int p = sub; p < BPB; p += 8) s += g_p1[b][p][col];
        red[col][sub] = s;
    }
    __syncthreads();
    if (tid < NP1) {
        float s = 0.f;
        #pragma unroll
        for (int u = 0; u < 8; u++) s += red[tid][u];
        tot[tid] = s;
    }
    __syncthreads();
    if (tid < 16) {
        sm[tid >> 2][tid & 3] = tot[tid] / fmaxf(tot[16 + (tid >> 2)], 1.0f);
        if (blk == 0 && tid < NL) g_cnts[b][tid] = tot[16 + tid];
    }
    __syncthreads();

    // ---- main loop: hinge + CE ----
    float hs[NL] = {0.f, 0.f, 0.f, 0.f};
    float wnll = 0.f;

    #pragma unroll
    for (int k = 0; k < KIT; k++) {
        const int i = base + k * TPB;
        float4 e0v = ldg_el_f4((const float4*)(e0)          + i, pol);
        float4 e1v = ldg_el_f4((const float4*)(e0 + NPIX)   + i, pol);
        float4 e2v = ldg_el_f4((const float4*)(e0 + 2*NPIX) + i, pol);
        float4 e3v = ldg_el_f4((const float4*)(e0 + 3*NPIX) + i, pol);
        int4   lv  = ldg_el_i4((const int4*)(l0) + i, pol);
        float4 g0v = __ldg((const float4*)(s0)          + i);
        float4 g1v = __ldg((const float4*)(s0 + NPIX)   + i);

        const float ed0[4] = {e0v.x, e0v.y, e0v.z, e0v.w};
        const float ed1[4] = {e1v.x, e1v.y, e1v.z, e1v.w};
        const float ed2[4] = {e2v.x, e2v.y, e2v.z, e2v.w};
        const float ed3[4] = {e3v.x, e3v.y, e3v.z, e3v.w};
        const int   lbs[4] = {lv.x, lv.y, lv.z, lv.w};
        const float ga[4]  = {g0v.x, g0v.y, g0v.z, g0v.w};
        const float gb[4]  = {g1v.x, g1v.y, g1v.z, g1v.w};

        #pragma unroll
        for (int p = 0; p < 4; p++) {
            const int L = lbs[p];
            if (L > 0) {
                const int li = L - 1;          // dynamic index into shared
                const float d0 = ed0[p] - sm[li][0];
                const float d1 = ed1[p] - sm[li][1];
                const float d2 = ed2[p] - sm[li][2];
                const float d3 = ed3[p] - sm[li][3];
                const float sq = d0*d0 + d1*d1 + d2*d2 + d3*d3;
                const float dist = sqrtf(sq);
                const float tt = fmaxf(dist - DELTA_V, 0.0f);
                const float hv = tt * tt;
                #pragma unroll
                for (int l = 0; l < NL; l++)
                    if (li == l) hs[l] += hv;
            }
            // weighted binary CE: nll = softplus(tgt ? (a-c) : (c-a))
            const float d  = ga[p] - gb[p];
            const float ax = fabsf(d);
            const int tgt  = (L > 0);
            const float hinge = tgt ? fmaxf(d, 0.f) : fmaxf(-d, 0.f);
            const float sp = hinge + __logf(1.0f + __expf(-ax));
            wnll += (tgt ? 1.0f : 0.5f) * sp;
        }
    }

    // block reduce 5 values -> per-block partial
    {
        __shared__ float shh[TPB / 32][NP2];
        const int wid = tid >> 5, lane = tid & 31;
        float vals[NP2] = {hs[0], hs[1], hs[2], hs[3], wnll};
        #pragma unroll
        for (int j = 0; j < NP2; j++) {
            float r = warp_sum(vals[j]);
            if (lane == 0) shh[wid][j] = r;
        }
        __syncthreads();
        if (tid < NP2) {
            float s = 0.f;
            #pragma unroll
            for (int w = 0; w < TPB / 32; w++) s += shh[w][tid];
            g_p2[b][blk][tid] = s;
        }
    }

    // ---- finalize in the last block (ticket; no waiting => no deadlock) ----
    __shared__ int sh_last;
    __threadfence();
    __syncthreads();
    if (tid == 0) sh_last = (atomicAdd(&g_t2, 1) == GB - 1);
    __syncthreads();
    if (!sh_last) return;

    __shared__ float fin[BB * NP2];       // 80 reduced values
    if (tid < BB * NP2) {
        const int bb = tid / NP2, j = tid % NP2;
        float s = 0.f;
        #pragma unroll
        for (int p = 0; p < BPB; p++) s += g_p2[bb][p][j];
        fin[tid] = s;
    }
    __syncthreads();
    if (tid == 0) {
        float var_tot = 0.f, wn = 0.f, cfg = 0.f;
        #pragma unroll
        for (int bb = 0; bb < BB; bb++) {
            float nlanes = 0.f, sv = 0.f;
            #pragma unroll
            for (int l = 0; l < NL; l++) {
                const float c = g_cnts[bb][l];
                if (c > 0.f) {
                    nlanes += 1.f;
                    sv += fin[bb * NP2 + l] / c;
                }
                cfg += c;
            }
            var_tot += sv / fmaxf(nlanes, 1.f);
            wn += fin[bb * NP2 + 4];
        }
        const float wsum = 0.5f * (float)(BB * NPIX) + 0.5f * cfg;
        // dist_loss == 0 identically (delta_d added to all pair distances);
        // reg_loss == 0.  loss = seg_ce + var.
        out[0] = wn / wsum + var_tot / (float)BB;
        g_t2 = 0;   // reset for the next graph replay
    }
}

// ---------------------------------------------------------------------------
extern "C" void kernel_launch(void* const* d_in, const int* in_sizes, int n_in,
                              void* d_out, int out_size) {
    const float* emb  = (const float*)d_in[0];  // [16,4,288,800] f32
    const float* bseg = (const float*)d_in[1];  // [16,2,288,800] f32
    const int*   lab  = (const int*)  d_in[2];  // [16,288,800]   i32
    float* out = (float*)d_out;
    (void)in_sizes; (void)n_in; (void)out_size;

    dim3 grid(BPB, BB);
    pass1_kernel<<<grid, TPB>>>(emb, lab);
    pass2_kernel<<<grid, TPB>>>(emb, bseg, lab, out);
}

// round 11
// speedup vs baseline: 1.1532x; 1.1532x over previous
#include <cuda_runtime.h>
#include <math.h>

// Problem constants
#define BB 16
#define NPIX (288 * 800)        // 230400 pixels per batch per plane
#define NVEC (NPIX / 4)         // 57600 float4 groups per plane per batch
#define BPB 45                  // blocks per batch -> 720 total blocks
#define GB  (BPB * BB)          // 720
#define TPB 256
#define KIT 5                   // exactly 5 groups/thread: 45*256*5 = 57600
#define NL 4                    // tracked labels 1..4 (label 0 stats dead)
#define NP1 21                  // 16 sums + 4 counts + wnll
#define DELTA_V 0.5f

// Scratch (device globals; allocation is forbidden)
__device__ float g_p1[BB][BPB][NP1];   // pass1 per-block partials
__device__ float g_p2[BB][BPB];        // pass2 per-block hvar partial
__device__ float g_cnts[BB][NL];       // written by pass2 blk==0 of each batch
__device__ float g_wnll[BB];           // written by pass2 blk==0 of each batch
__device__ int   g_t2;                 // finalize ticket (reset each replay)

__device__ __forceinline__ float warp_sum(float v) {
    #pragma unroll
    for (int o = 16; o > 0; o >>= 1) v += __shfl_xor_sync(0xffffffffu, v, o);
    return v;
}

// ---------------------------------------------------------------------------
// Pass 1: per-(b,label) embedding sums + counts + weighted CE.
// grid=(45,16), block=256, 5 blocks/SM.
__global__ void __launch_bounds__(TPB, 5)
pass1_kernel(const float* __restrict__ emb,
             const float* __restrict__ seg2,
             const int*   __restrict__ lab) {
    const int b   = blockIdx.y;
    const int blk = blockIdx.x;
    const int tid = threadIdx.x;
    const float* e0 = emb  + (size_t)b * 4 * NPIX;
    const float* s0 = seg2 + (size_t)b * 2 * NPIX;
    const int*   l0 = lab  + (size_t)b * NPIX;
    const int base = blk * (TPB * KIT) + tid;

    float acc[NL][4];
    float cnt[NL];
    #pragma unroll
    for (int l = 0; l < NL; l++) {
        cnt[l] = 0.f;
        #pragma unroll
        for (int d = 0; d < 4; d++) acc[l][d] = 0.f;
    }
    float wnll = 0.f;

    #pragma unroll
    for (int k = 0; k < KIT; k++) {
        const int i = base + k * TPB;
        float4 e0v = __ldg((const float4*)(e0)          + i);
        float4 e1v = __ldg((const float4*)(e0 + NPIX)   + i);
        float4 e2v = __ldg((const float4*)(e0 + 2*NPIX) + i);
        float4 e3v = __ldg((const float4*)(e0 + 3*NPIX) + i);
        int4   lv  = __ldg((const int4*)(l0) + i);
        float4 g0v = __ldg((const float4*)(s0)          + i);
        float4 g1v = __ldg((const float4*)(s0 + NPIX)   + i);

        const float ed0[4] = {e0v.x, e0v.y, e0v.z, e0v.w};
        const float ed1[4] = {e1v.x, e1v.y, e1v.z, e1v.w};
        const float ed2[4] = {e2v.x, e2v.y, e2v.z, e2v.w};
        const float ed3[4] = {e3v.x, e3v.y, e3v.z, e3v.w};
        const int   lbs[4] = {lv.x, lv.y, lv.z, lv.w};
        const float ga[4]  = {g0v.x, g0v.y, g0v.z, g0v.w};
        const float gb[4]  = {g1v.x, g1v.y, g1v.z, g1v.w};

        #pragma unroll
        for (int p = 0; p < 4; p++) {
            const int L = lbs[p];
            #pragma unroll
            for (int l = 0; l < NL; l++) {
                if (L == l + 1) {
                    acc[l][0] += ed0[p];
                    acc[l][1] += ed1[p];
                    acc[l][2] += ed2[p];
                    acc[l][3] += ed3[p];
                    cnt[l]    += 1.f;
                }
            }
            // weighted binary CE: nll = softplus(tgt ? (a-c) : (c-a))
            const float d  = ga[p] - gb[p];
            const float ax = fabsf(d);
            const int tgt  = (L > 0);
            const float hinge = tgt ? fmaxf(d, 0.f) : fmaxf(-d, 0.f);
            const float sp = hinge + __logf(1.0f + __expf(-ax));
            wnll += (tgt ? 1.0f : 0.5f) * sp;
        }
    }

    // block reduce 21 values -> per-block partial
    __shared__ float sh[TPB / 32][NP1];
    const int wid = tid >> 5, lane = tid & 31;
    float vals[NP1];
    #pragma unroll
    for (int l = 0; l < NL; l++) {
        #pragma unroll
        for (int d = 0; d < 4; d++) vals[l * 4 + d] = acc[l][d];
        vals[16 + l] = cnt[l];
    }
    vals[20] = wnll;
    #pragma unroll
    for (int j = 0; j < NP1; j++) {
        float r = warp_sum(vals[j]);
        if (lane == 0) sh[wid][j] = r;
    }
    __syncthreads();
    if (tid < NP1) {
        float s = 0.f;
        #pragma unroll
        for (int w = 0; w < TPB / 32; w++) s += sh[w][tid];
        g_p1[b][blk][tid] = s;
    }
}

// ---------------------------------------------------------------------------
// Pass 2: branchless hinge via 5-entry label tables (mu[0]=0, inv[0]=0),
// single accumulator hvar = sum over pixels of hinge(pix)/count(label(pix)).
// grid=(45,16), block=256, 5 blocks/SM (same occupancy config as R8 pass).
__global__ void __launch_bounds__(TPB, 5)
pass2_kernel(const float* __restrict__ emb,
             const int*   __restrict__ lab,
             float* __restrict__ out) {
    const int b   = blockIdx.y;
    const int blk = blockIdx.x;
    const int tid = threadIdx.x;
    const float* e0 = emb + (size_t)b * 4 * NPIX;
    const int*   l0 = lab + (size_t)b * NPIX;
    const int base = blk * (TPB * KIT) + tid;

    // ---- reduce this batch's pass1 partials -> label tables ----
    __shared__ float red[NP1][8];
    __shared__ float tot[NP1];
    __shared__ float4 smu[NL + 1];   // [0] = zeros (background)
    __shared__ float  sinv[NL + 1];  // [0] = 0
    if (tid < NP1 * 8) {
        const int col = tid >> 3, sub = tid & 7;
        float s = 0.f;
        for (int p = sub; p < BPB; p += 8) s += g_p1[b][p][col];
        red[col][sub] = s;
    }
    __syncthreads();
    if (tid < NP1) {
        float s = 0.f;
        #pragma unroll
        for (int u = 0; u < 8; u++) s += red[tid][u];
        tot[tid] = s;
    }
    __syncthreads();
    if (tid <= NL) {
        if (tid == 0) {
            smu[0] = make_float4(0.f, 0.f, 0.f, 0.f);
            sinv[0] = 0.f;
        } else {
            const int l = tid - 1;
            const float c = tot[16 + l];
            const float inv = 1.0f / fmaxf(c, 1.0f);
            smu[tid] = make_float4(tot[l * 4 + 0] * inv, tot[l * 4 + 1] * inv,
                                   tot[l * 4 + 2] * inv, tot[l * 4 + 3] * inv);
            sinv[tid] = (c > 0.f) ? inv : 0.f;
            if (blk == 0) g_cnts[b][l] = c;
        }
        if (blk == 0 && tid == 0) g_wnll[b] = tot[20];
    }
    __syncthreads();

    // ---- main loop: branchless hinge ----
    float hvar = 0.f;

    #pragma unroll
    for (int k = 0; k < KIT; k++) {
        const int i = base + k * TPB;
        float4 e0v = __ldg((const float4*)(e0)          + i);
        float4 e1v = __ldg((const float4*)(e0 + NPIX)   + i);
        float4 e2v = __ldg((const float4*)(e0 + 2*NPIX) + i);
        float4 e3v = __ldg((const float4*)(e0 + 3*NPIX) + i);
        int4   lv  = __ldg((const int4*)(l0) + i);

        const float ed0[4] = {e0v.x, e0v.y, e0v.z, e0v.w};
        const float ed1[4] = {e1v.x, e1v.y, e1v.z, e1v.w};
        const float ed2[4] = {e2v.x, e2v.y, e2v.z, e2v.w};
        const float ed3[4] = {e3v.x, e3v.y, e3v.z, e3v.w};
        const int   lbs[4] = {lv.x, lv.y, lv.z, lv.w};

        #pragma unroll
        for (int p = 0; p < 4; p++) {
            const int L = lbs[p];           // 0..4, direct table index
            const float4 mu = smu[L];       // LDS.128
            const float w   = sinv[L];      // LDS.32 (0 for background)
            const float d0 = ed0[p] - mu.x;
            const float d1 = ed1[p] - mu.y;
            const float d2 = ed2[p] - mu.z;
            const float d3 = ed3[p] - mu.w;
            const float sq = d0*d0 + d1*d1 + d2*d2 + d3*d3;
            const float dist = sqrtf(sq);
            const float t = fmaxf(dist - DELTA_V, 0.0f);
            hvar = fmaf(t * t, w, hvar);
        }
    }

    // block reduce 1 value -> per-block partial
    {
        __shared__ float shh[TPB / 32];
        const int wid = tid >> 5, lane = tid & 31;
        float r = warp_sum(hvar);
        if (lane == 0) shh[wid] = r;
        __syncthreads();
        if (tid == 0) {
            float s = 0.f;
            #pragma unroll
            for (int w = 0; w < TPB / 32; w++) s += shh[w];
            g_p2[b][blk] = s;
        }
    }

    // ---- finalize in the last block (ticket; no waiting => no deadlock) ----
    __shared__ int sh_last;
    __threadfence();
    __syncthreads();
    if (tid == 0) sh_last = (atomicAdd(&g_t2, 1) == GB - 1);
    __syncthreads();
    if (!sh_last) return;

    __shared__ float fin[BB];
    if (tid < BB) {
        float s = 0.f;
        #pragma unroll
        for (int p = 0; p < BPB; p++) s += g_p2[tid][p];
        fin[tid] = s;
    }
    __syncthreads();
    if (tid == 0) {
        float var_tot = 0.f, wn = 0.f, cfg = 0.f;
        #pragma unroll
        for (int bb = 0; bb < BB; bb++) {
            float nlanes = 0.f;
            #pragma unroll
            for (int l = 0; l < NL; l++) {
                const float c = g_cnts[bb][l];
                if (c > 0.f) nlanes += 1.f;
                cfg += c;
            }
            var_tot += fin[bb] / fmaxf(nlanes, 1.f);
            wn += g_wnll[bb];
        }
        const float wsum = 0.5f * (float)(BB * NPIX) + 0.5f * cfg;
        // dist_loss == 0 identically (delta_d added to all pair distances);
        // reg_loss == 0.  loss = seg_ce + var.
        out[0] = wn / wsum + var_tot / (float)BB;
        g_t2 = 0;   // reset for the next graph replay
    }
}

// ---------------------------------------------------------------------------
extern "C" void kernel_launch(void* const* d_in, const int* in_sizes, int n_in,
                              void* d_out, int out_size) {
    const float* emb  = (const float*)d_in[0];  // [16,4,288,800] f32
    const float* bseg = (const float*)d_in[1];  // [16,2,288,800] f32
    const int*   lab  = (const int*)  d_in[2];  // [16,288,800]   i32
    float* out = (float*)d_out;
    (void)in_sizes; (void)n_in; (void)out_size;

    dim3 grid(BPB, BB);
    pass1_kernel<<<grid, TPB>>>(emb, bseg, lab);
    pass2_kernel<<<grid, TPB>>>(emb, lab, out);
}